// round 2
// baseline (speedup 1.0000x reference)
#include <cuda_runtime.h>
#include <math.h>

#define B_    64
#define H_    8
#define N_    16384
#define M_    64
#define C_    1024
#define IVH_  198          // 3*M + 6
#define HIVH  (H_ * IVH_)  // 1584
#define BH_   (B_ * H_)    // 512
#define PITCH 68           // floats; 272B = 17*16B -> 16B-aligned rows, conflict-free
#define TILE_R 256
#define NCHUNK 8
#define CHUNK_N (N_ / NCHUNK)  // 2048

// ---------------- scratch (device globals; no allocation allowed) ----------
__device__ float g_iv[B_ * HIVH];
__device__ float g_k[BH_ * M_];
__device__ float g_par[BH_ * 8];             // beta, g, s0, s1, s2, gamma, knorm
__device__ float g_partial[NCHUNK * BH_ * M_];

// ---------------- kernel 1: iv = x @ W + b  (64 x 1584 x 1024) -------------
__global__ __launch_bounds__(256) void k_gemm(const float* __restrict__ x,
                                              const float* __restrict__ W,
                                              const float* __restrict__ bias) {
    __shared__ float xs[64][33];
    __shared__ float ws[32][33];
    int c0  = blockIdx.x * 32;
    int col = threadIdx.x & 31;
    int rg  = threadIdx.x >> 5;      // 0..7
    float acc[8];
#pragma unroll
    for (int j = 0; j < 8; j++) acc[j] = 0.f;

    for (int kc = 0; kc < C_; kc += 32) {
#pragma unroll
        for (int i = 0; i < 8; i++) {
            int idx = threadIdx.x + i * 256;
            int r = idx >> 5, kk = idx & 31;
            xs[r][kk] = x[r * C_ + kc + kk];
        }
#pragma unroll
        for (int i = 0; i < 4; i++) {
            int idx = threadIdx.x + i * 256;
            int rr = idx >> 5, cc = idx & 31;
            int c = c0 + cc;
            ws[rr][cc] = (c < HIVH) ? W[(size_t)(kc + rr) * HIVH + c] : 0.f;
        }
        __syncthreads();
#pragma unroll
        for (int k = 0; k < 32; k++) {
            float wv = ws[k][col];
#pragma unroll
            for (int j = 0; j < 8; j++)
                acc[j] = fmaf(xs[j * 8 + rg][k], wv, acc[j]);
        }
        __syncthreads();
    }
    int c = c0 + col;
    if (c < HIVH) {
        float bb = bias[c];
#pragma unroll
        for (int j = 0; j < 8; j++)
            g_iv[(size_t)(j * 8 + rg) * HIVH + c] = acc[j] + bb;
    }
}

// ---------------- kernel 2: activations / parameter split ------------------
__global__ __launch_bounds__(64) void k_act(float* __restrict__ out_e,
                                            float* __restrict__ out_a) {
    int bh = blockIdx.x;                    // 0..511
    int b = bh >> 3, h = bh & 7;
    const float* iv = g_iv + (size_t)b * HIVH + h * IVH_;
    int t = threadIdx.x;                    // 0..63
    __shared__ float red[2];

    float kv = iv[t];
    g_k[(size_t)bh * M_ + t] = kv;
    float sq = kv * kv;
#pragma unroll
    for (int o = 16; o; o >>= 1) sq += __shfl_xor_sync(0xffffffffu, sq, o);
    if ((t & 31) == 0) red[t >> 5] = sq;

    float e_in = iv[M_ + 6 + t];
    out_e[(size_t)bh * M_ + t] = 1.f / (1.f + expf(-e_in));
    out_a[(size_t)bh * M_ + t] = iv[2 * M_ + 6 + t];
    __syncthreads();

    if (t == 0) {
        float knorm = sqrtf(red[0] + red[1]);
        float bx = iv[M_];
        float beta = (bx > 20.f) ? bx : log1pf(expf(bx));
        float g = 1.f / (1.f + expf(-iv[M_ + 1]));
        float s0 = iv[M_ + 2], s1 = iv[M_ + 3], s2 = iv[M_ + 4];
        float mx = fmaxf(s0, fmaxf(s1, s2));
        float e0 = expf(s0 - mx), e1 = expf(s1 - mx), e2 = expf(s2 - mx);
        float inv = 1.f / (e0 + e1 + e2);
        float gx = iv[M_ + 5];
        float gamma = 1.f + ((gx > 20.f) ? gx : log1pf(expf(gx)));
        float* p = g_par + (size_t)bh * 8;
        p[0] = beta; p[1] = g; p[2] = e0 * inv; p[3] = e1 * inv;
        p[4] = e2 * inv; p[5] = gamma; p[6] = knorm;
    }
}

// ---------------- kernel 3: logits = beta * cos(k, mem_n) -------------------
// writes logits into the d_out w-region (overwritten later by k_addr)
__global__ __launch_bounds__(256) void k_cos(const float* __restrict__ mem,
                                             float* __restrict__ logits) {
    extern __shared__ float tile[];          // TILE_R * PITCH floats
    __shared__ float ks[8][64];
    __shared__ float p_beta[8], p_kn[8];
    int b = blockIdx.y, chunk = blockIdx.x;
    int tid = threadIdx.x;

    for (int i = tid; i < 512; i += 256) ks[i >> 6][i & 63] = g_k[(size_t)b * 512 + i];
    if (tid < 8) {
        p_beta[tid] = g_par[((size_t)b * 8 + tid) * 8 + 0];
        p_kn[tid]   = g_par[((size_t)b * 8 + tid) * 8 + 6];
    }
    __syncthreads();

    for (int st = 0; st < CHUNK_N; st += TILE_R) {
        int n0 = chunk * CHUNK_N + st;
        const float4* src = (const float4*)(mem + ((size_t)b * N_ + n0) * M_);
#pragma unroll
        for (int i = 0; i < 16; i++) {
            int idx = tid + i * 256;
            int r = idx >> 4, c4 = idx & 15;
            float4 v = src[r * 16 + c4];
            float* d = tile + r * PITCH + c4 * 4;
            d[0] = v.x; d[1] = v.y; d[2] = v.z; d[3] = v.w;
        }
        __syncthreads();

        float acc[8];
#pragma unroll
        for (int h = 0; h < 8; h++) acc[h] = 0.f;
        float nn = 0.f;
        const float* row = tile + tid * PITCH;
#pragma unroll
        for (int m = 0; m < 64; m += 4) {
            float4 v = *(const float4*)(row + m);
            nn = fmaf(v.x, v.x, nn); nn = fmaf(v.y, v.y, nn);
            nn = fmaf(v.z, v.z, nn); nn = fmaf(v.w, v.w, nn);
#pragma unroll
            for (int h = 0; h < 8; h++) {
                float4 kv = *(const float4*)(&ks[h][m]);
                acc[h] = fmaf(v.x, kv.x, acc[h]);
                acc[h] = fmaf(v.y, kv.y, acc[h]);
                acc[h] = fmaf(v.z, kv.z, acc[h]);
                acc[h] = fmaf(v.w, kv.w, acc[h]);
            }
        }
        float mn = sqrtf(nn);
        int n = n0 + tid;
#pragma unroll
        for (int h = 0; h < 8; h++) {
            float den = p_kn[h] * mn + 1e-16f;
            logits[((size_t)(b * 8 + h)) * N_ + n] = p_beta[h] * acc[h] / den;
        }
        __syncthreads();
    }
}

// ---------------- block reductions ------------------------------------------
__device__ __forceinline__ float blockReduceSum(float v, float* red) {
#pragma unroll
    for (int o = 16; o; o >>= 1) v += __shfl_xor_sync(0xffffffffu, v, o);
    int w = threadIdx.x >> 5, l = threadIdx.x & 31;
    if (l == 0) red[w] = v;
    __syncthreads();
    if (w == 0) {
        v = (l < 8) ? red[l] : 0.f;
#pragma unroll
        for (int o = 4; o; o >>= 1) v += __shfl_xor_sync(0xffffffffu, v, o);
        if (l == 0) red[0] = v;
    }
    __syncthreads();
    v = red[0];
    __syncthreads();
    return v;
}

__device__ __forceinline__ float blockReduceMax(float v, float* red) {
#pragma unroll
    for (int o = 16; o; o >>= 1) v = fmaxf(v, __shfl_xor_sync(0xffffffffu, v, o));
    int w = threadIdx.x >> 5, l = threadIdx.x & 31;
    if (l == 0) red[w] = v;
    __syncthreads();
    if (w == 0) {
        v = (l < 8) ? red[l] : -1e30f;
#pragma unroll
        for (int o = 4; o; o >>= 1) v = fmaxf(v, __shfl_xor_sync(0xffffffffu, v, o));
        if (l == 0) red[0] = v;
    }
    __syncthreads();
    v = red[0];
    __syncthreads();
    return v;
}

// ---------------- kernel 4: addressing (softmax/gate/shift/sharpen) ---------
__global__ __launch_bounds__(256) void k_addr(float* __restrict__ wbuf,
                                              const float* __restrict__ wprev) {
    extern __shared__ float sw[];            // N_ floats
    __shared__ float red[8];
    int bh = blockIdx.x;
    const float* par = g_par + (size_t)bh * 8;
    float g = par[1], s0 = par[2], s1 = par[3], s2 = par[4], gamma = par[5];
    float* lrow = wbuf + (size_t)bh * N_;
    const float* wprow = wprev + (size_t)bh * N_;
    int tid = threadIdx.x;

    float mx = -1e30f;
#pragma unroll 4
    for (int i = 0; i < 64; i++) {
        int n = tid + i * 256;
        float v = lrow[n];
        sw[n] = v;
        mx = fmaxf(mx, v);
    }
    mx = blockReduceMax(mx, red);

    float sum = 0.f;
#pragma unroll 4
    for (int i = 0; i < 64; i++) {
        int n = tid + i * 256;
        float e = expf(sw[n] - mx);
        sw[n] = e;
        sum += e;
    }
    sum = blockReduceSum(sum, red);
    float invs = 1.f / sum;
    float gc = 1.f - g;

#pragma unroll 4
    for (int i = 0; i < 64; i++) {
        int n = tid + i * 256;
        sw[n] = fmaf(g * invs, sw[n], gc * wprow[n]);   // wg
    }
    __syncthreads();

    float wp[64];
    float lsum = 0.f;
#pragma unroll 4
    for (int i = 0; i < 64; i++) {
        int n = tid + i * 256;
        int nm = (n == 0) ? (N_ - 1) : (n - 1);
        int np = (n == N_ - 1) ? 0 : (n + 1);
        float ws = s0 * sw[nm] + s1 * sw[n] + s2 * sw[np];
        float v = exp2f(gamma * log2f(ws));
        wp[i] = v;
        lsum += v;
    }
    float tot = blockReduceSum(lsum, red);
    float inv = 1.f / (tot + 1e-16f);
#pragma unroll 4
    for (int i = 0; i < 64; i++)
        lrow[tid + i * 256] = wp[i] * inv;
}

// ---------------- kernel 5: read_data partials (w . memory) -----------------
__global__ __launch_bounds__(256) void k_read(const float* __restrict__ mem,
                                              const float* __restrict__ wbuf) {
    extern __shared__ float tile[];          // TILE_R * PITCH
    __shared__ float wsh[8][256];
    int b = blockIdx.y, chunk = blockIdx.x;
    int tid = threadIdx.x;
    int h = tid >> 5, lane = tid & 31;
    float acc0 = 0.f, acc1 = 0.f;

    for (int st = 0; st < CHUNK_N; st += TILE_R) {
        int n0 = chunk * CHUNK_N + st;
        const float4* src = (const float4*)(mem + ((size_t)b * N_ + n0) * M_);
#pragma unroll
        for (int i = 0; i < 16; i++) {
            int idx = tid + i * 256;
            int r = idx >> 4, c4 = idx & 15;
            float4 v = src[r * 16 + c4];
            float* d = tile + r * PITCH + c4 * 4;
            d[0] = v.x; d[1] = v.y; d[2] = v.z; d[3] = v.w;
        }
#pragma unroll
        for (int i = 0; i < 8; i++) {
            int idx = tid + i * 256;
            int hh = idx >> 8, nn = idx & 255;
            wsh[hh][nn] = wbuf[((size_t)(b * 8 + hh)) * N_ + n0 + nn];
        }
        __syncthreads();
#pragma unroll 8
        for (int n = 0; n < 256; n++) {
            float wv = wsh[h][n];
            float2 mv = *(const float2*)(tile + n * PITCH + lane * 2);
            acc0 = fmaf(wv, mv.x, acc0);
            acc1 = fmaf(wv, mv.y, acc1);
        }
        __syncthreads();
    }
    float* dst = g_partial + ((size_t)chunk * B_ + b) * (H_ * M_) + h * M_ + lane * 2;
    dst[0] = acc0;
    dst[1] = acc1;
}

// ---------------- kernel 6: reduce partials -> read_data --------------------
__global__ __launch_bounds__(256) void k_final(float* __restrict__ out) {
    int i = blockIdx.x * 256 + threadIdx.x;  // < 32768
    float s = 0.f;
#pragma unroll
    for (int c = 0; c < NCHUNK; c++)
        s += g_partial[(size_t)c * BH_ * M_ + i];
    out[i] = s;
}

// ---------------- launch -----------------------------------------------------
extern "C" void kernel_launch(void* const* d_in, const int* in_sizes, int n_in,
                              void* d_out, int out_size) {
    const float* x     = (const float*)d_in[0];
    const float* mem   = (const float*)d_in[1];
    const float* wprev = (const float*)d_in[2];
    const float* W     = (const float*)d_in[3];
    const float* bias  = (const float*)d_in[4];
    float* out = (float*)d_out;
    float* out_read = out;                         // 32768
    float* out_w    = out + 32768;                 // 8388608
    float* out_e    = out + 32768 + (size_t)BH_ * N_;
    float* out_a    = out_e + 32768;

    cudaFuncSetAttribute(k_cos,  cudaFuncAttributeMaxDynamicSharedMemorySize, TILE_R * PITCH * 4);
    cudaFuncSetAttribute(k_addr, cudaFuncAttributeMaxDynamicSharedMemorySize, N_ * 4);
    cudaFuncSetAttribute(k_read, cudaFuncAttributeMaxDynamicSharedMemorySize, TILE_R * PITCH * 4);

    k_gemm<<<50, 256>>>(x, W, bias);
    k_act<<<BH_, 64>>>(out_e, out_a);
    k_cos<<<dim3(NCHUNK, B_), 256, TILE_R * PITCH * 4>>>(mem, out_w);
    k_addr<<<BH_, 256, N_ * 4>>>(out_w, wprev);
    k_read<<<dim3(NCHUNK, B_), 256, TILE_R * PITCH * 4>>>(mem, out_w);
    k_final<<<128, 256>>>(out_read);
}

// round 4
// speedup vs baseline: 2.0471x; 2.0471x over previous
#include <cuda_runtime.h>
#include <math.h>

#define B_    64
#define H_    8
#define N_    16384
#define M_    64
#define C_    1024
#define IVH_  198          // 3*M + 6
#define HIVH  (H_ * IVH_)  // 1584
#define BH_   (B_ * H_)    // 512
#define PITCH 68           // floats; 272B -> 16B-aligned rows, conflict-free
#define TILE_R 256
#define NCHUNK 16
#define CHUNK_N (N_ / NCHUNK)  // 1024
#define KSPLIT 8

// ---------------- scratch (device globals; no allocation allowed) ----------
__device__ float  g_ivp[KSPLIT][B_ * HIVH];
__device__ float  g_k[BH_ * M_];
__device__ float  g_par[BH_ * 8];            // beta, g, s0, s1, s2, gamma, knorm
__device__ float2 g_ms[BH_ * NCHUNK];        // per-chunk online (max, expsum)
__device__ float  g_partial[NCHUNK * BH_ * M_];

// ---------------- kernel 1: iv partials = x @ W  (K-split by 8) ------------
__global__ __launch_bounds__(256) void k_gemm(const float* __restrict__ x,
                                              const float* __restrict__ W) {
    __shared__ float xs[64][33];
    __shared__ float ws[32][33];
    int c0  = blockIdx.x * 32;
    int ks  = blockIdx.y;
    int col = threadIdx.x & 31;
    int rg  = threadIdx.x >> 5;      // 0..7
    float acc[8];
#pragma unroll
    for (int j = 0; j < 8; j++) acc[j] = 0.f;

    int k0 = ks * (C_ / KSPLIT);
    for (int kc = k0; kc < k0 + C_ / KSPLIT; kc += 32) {
#pragma unroll
        for (int i = 0; i < 8; i++) {
            int idx = threadIdx.x + i * 256;
            int r = idx >> 5, kk = idx & 31;
            xs[r][kk] = x[r * C_ + kc + kk];
        }
#pragma unroll
        for (int i = 0; i < 4; i++) {
            int idx = threadIdx.x + i * 256;
            int rr = idx >> 5, cc = idx & 31;
            int c = c0 + cc;
            ws[rr][cc] = (c < HIVH) ? W[(size_t)(kc + rr) * HIVH + c] : 0.f;
        }
        __syncthreads();
#pragma unroll
        for (int k = 0; k < 32; k++) {
            float wv = ws[k][col];
#pragma unroll
            for (int j = 0; j < 8; j++)
                acc[j] = fmaf(xs[j * 8 + rg][k], wv, acc[j]);
        }
        __syncthreads();
    }
    int c = c0 + col;
    if (c < HIVH) {
#pragma unroll
        for (int j = 0; j < 8; j++)
            g_ivp[ks][(size_t)(j * 8 + rg) * HIVH + c] = acc[j];
    }
}

// ---------------- kernel 2: reduce K-split + activations -------------------
__device__ __forceinline__ float iv_sum(int b, int off, const float* bias) {
    float s = bias[off];
#pragma unroll
    for (int ks = 0; ks < KSPLIT; ks++) s += g_ivp[ks][(size_t)b * HIVH + off];
    return s;
}

__global__ __launch_bounds__(64) void k_act(const float* __restrict__ bias,
                                            float* __restrict__ out_e,
                                            float* __restrict__ out_a) {
    int bh = blockIdx.x;                    // 0..511
    int b = bh >> 3, h = bh & 7;
    int base = h * IVH_;
    int t = threadIdx.x;                    // 0..63
    __shared__ float red[2];

    float kv = iv_sum(b, base + t, bias);
    g_k[(size_t)bh * M_ + t] = kv;
    float sq = kv * kv;
#pragma unroll
    for (int o = 16; o; o >>= 1) sq += __shfl_xor_sync(0xffffffffu, sq, o);
    if ((t & 31) == 0) red[t >> 5] = sq;

    float e_in = iv_sum(b, base + M_ + 6 + t, bias);
    out_e[(size_t)bh * M_ + t] = 1.f / (1.f + __expf(-e_in));
    out_a[(size_t)bh * M_ + t] = iv_sum(b, base + 2 * M_ + 6 + t, bias);
    __syncthreads();

    if (t == 0) {
        float knorm = sqrtf(red[0] + red[1]);
        float bx = iv_sum(b, base + M_, bias);
        float beta = (bx > 20.f) ? bx : log1pf(expf(bx));
        float g = 1.f / (1.f + expf(-iv_sum(b, base + M_ + 1, bias)));
        float s0 = iv_sum(b, base + M_ + 2, bias);
        float s1 = iv_sum(b, base + M_ + 3, bias);
        float s2 = iv_sum(b, base + M_ + 4, bias);
        float mx = fmaxf(s0, fmaxf(s1, s2));
        float e0 = expf(s0 - mx), e1 = expf(s1 - mx), e2 = expf(s2 - mx);
        float inv = 1.f / (e0 + e1 + e2);
        float gx = iv_sum(b, base + M_ + 5, bias);
        float gamma = 1.f + ((gx > 20.f) ? gx : log1pf(expf(gx)));
        float* p = g_par + (size_t)bh * 8;
        p[0] = beta; p[1] = g; p[2] = e0 * inv; p[3] = e1 * inv;
        p[4] = e2 * inv; p[5] = gamma; p[6] = knorm;
    }
}

// ---------------- kernel 3: logits + per-chunk online softmax stats --------
__global__ __launch_bounds__(256) void k_cos(const float* __restrict__ mem,
                                             float* __restrict__ logits) {
    extern __shared__ float tile[];          // TILE_R * PITCH floats
    __shared__ float ksh[8][64];
    __shared__ float p_beta[8], p_kn[8];
    __shared__ float red_m[8][8], red_s[8][8];
    int b = blockIdx.y, chunk = blockIdx.x;
    int tid = threadIdx.x;
    int w = tid >> 5, lane = tid & 31;

    for (int i = tid; i < 512; i += 256) ksh[i >> 6][i & 63] = g_k[(size_t)b * 512 + i];
    if (tid < 8) {
        p_beta[tid] = g_par[((size_t)b * 8 + tid) * 8 + 0];
        p_kn[tid]   = g_par[((size_t)b * 8 + tid) * 8 + 6];
    }
    __syncthreads();

    float mloc[8], sloc[8];
#pragma unroll
    for (int h = 0; h < 8; h++) { mloc[h] = -1e30f; sloc[h] = 0.f; }

    for (int st = 0; st < CHUNK_N; st += TILE_R) {
        int n0 = chunk * CHUNK_N + st;
        const float4* src = (const float4*)(mem + ((size_t)b * N_ + n0) * M_);
#pragma unroll
        for (int i = 0; i < 16; i++) {
            int idx = tid + i * 256;
            int r = idx >> 4, c4 = idx & 15;
            float4 v = src[r * 16 + c4];
            float* d = tile + r * PITCH + c4 * 4;
            d[0] = v.x; d[1] = v.y; d[2] = v.z; d[3] = v.w;
        }
        __syncthreads();

        float acc[8];
#pragma unroll
        for (int h = 0; h < 8; h++) acc[h] = 0.f;
        float nn = 0.f;
        const float* row = tile + tid * PITCH;
#pragma unroll
        for (int m = 0; m < 64; m += 4) {
            float4 v = *(const float4*)(row + m);
            nn = fmaf(v.x, v.x, nn); nn = fmaf(v.y, v.y, nn);
            nn = fmaf(v.z, v.z, nn); nn = fmaf(v.w, v.w, nn);
#pragma unroll
            for (int h = 0; h < 8; h++) {
                float4 kv = *(const float4*)(&ksh[h][m]);
                acc[h] = fmaf(v.x, kv.x, acc[h]);
                acc[h] = fmaf(v.y, kv.y, acc[h]);
                acc[h] = fmaf(v.z, kv.z, acc[h]);
                acc[h] = fmaf(v.w, kv.w, acc[h]);
            }
        }
        float mn = sqrtf(nn);
        int n = n0 + tid;
#pragma unroll
        for (int h = 0; h < 8; h++) {
            float den = p_kn[h] * mn + 1e-16f;
            float l = p_beta[h] * acc[h] / den;
            logits[((size_t)(b * 8 + h)) * N_ + n] = l;
            float nm = fmaxf(mloc[h], l);
            sloc[h] = sloc[h] * __expf(mloc[h] - nm) + __expf(l - nm);
            mloc[h] = nm;
        }
        __syncthreads();
    }

    // reduce (max, expsum) across 256 threads for each head
#pragma unroll
    for (int o = 16; o; o >>= 1) {
#pragma unroll
        for (int h = 0; h < 8; h++) {
            float om = __shfl_xor_sync(0xffffffffu, mloc[h], o);
            float os = __shfl_xor_sync(0xffffffffu, sloc[h], o);
            float nm = fmaxf(mloc[h], om);
            sloc[h] = sloc[h] * __expf(mloc[h] - nm) + os * __expf(om - nm);
            mloc[h] = nm;
        }
    }
    if (lane == 0) {
#pragma unroll
        for (int h = 0; h < 8; h++) { red_m[w][h] = mloc[h]; red_s[w][h] = sloc[h]; }
    }
    __syncthreads();
    if (tid < 8) {
        float m = -1e30f, s = 0.f;
#pragma unroll
        for (int ww = 0; ww < 8; ww++) {
            float om = red_m[ww][tid], os = red_s[ww][tid];
            float nm = fmaxf(m, om);
            s = s * __expf(m - nm) + os * __expf(om - nm);
            m = nm;
        }
        g_ms[((size_t)b * 8 + tid) * NCHUNK + chunk] = make_float2(m, s);
    }
}

// ---------------- block reduction (16 warps) --------------------------------
__device__ __forceinline__ float blockReduceSum16(float v, float* red) {
#pragma unroll
    for (int o = 16; o; o >>= 1) v += __shfl_xor_sync(0xffffffffu, v, o);
    int w = threadIdx.x >> 5, l = threadIdx.x & 31;
    if (l == 0) red[w] = v;
    __syncthreads();
    if (w == 0) {
        v = (l < 16) ? red[l] : 0.f;
#pragma unroll
        for (int o = 8; o; o >>= 1) v += __shfl_xor_sync(0xffffffffu, v, o);
        if (l == 0) red[0] = v;
    }
    __syncthreads();
    v = red[0];
    __syncthreads();
    return v;
}

// ---------------- kernel 4: addressing (gate/shift/sharpen) -----------------
__global__ __launch_bounds__(512) void k_addr(float* __restrict__ wbuf,
                                              const float* __restrict__ wprev) {
    extern __shared__ float sw[];            // N_ floats (wg values)
    __shared__ float red[16];
    int bh = blockIdx.x;
    const float* par = g_par + (size_t)bh * 8;
    float g = par[1], s0 = par[2], s1 = par[3], s2 = par[4], gamma = par[5];
    float gc = 1.f - g;
    float* lrow = wbuf + (size_t)bh * N_;
    const float* wprow = wprev + (size_t)bh * N_;
    int tid = threadIdx.x;

    // combine per-chunk softmax stats (redundantly per thread; L1-broadcast)
    float M = -1e30f, S = 0.f;
#pragma unroll
    for (int c = 0; c < NCHUNK; c++) {
        float2 p = g_ms[(size_t)bh * NCHUNK + c];
        float nm = fmaxf(M, p.x);
        S = S * __expf(M - nm) + p.y * __expf(p.x - nm);
        M = nm;
    }
    float ginvS = g / S;

#pragma unroll 4
    for (int i = 0; i < 32; i++) {
        int n = tid + i * 512;
        float wc = __expf(lrow[n] - M);
        sw[n] = fmaf(ginvS, wc, gc * wprow[n]);          // wg
    }
    __syncthreads();

    float lsum = 0.f;
#pragma unroll 4
    for (int i = 0; i < 32; i++) {
        int n = tid + i * 512;
        int nm = (n == 0) ? (N_ - 1) : (n - 1);
        int np = (n == N_ - 1) ? 0 : (n + 1);
        float ws = s0 * sw[nm] + s1 * sw[n] + s2 * sw[np];
        lsum += exp2f(gamma * __log2f(ws));
    }
    float tot = blockReduceSum16(lsum, red);
    float inv = 1.f / (tot + 1e-16f);

#pragma unroll 4
    for (int i = 0; i < 32; i++) {
        int n = tid + i * 512;
        int nm = (n == 0) ? (N_ - 1) : (n - 1);
        int np = (n == N_ - 1) ? 0 : (n + 1);
        float ws = s0 * sw[nm] + s1 * sw[n] + s2 * sw[np];
        lrow[n] = exp2f(gamma * __log2f(ws)) * inv;
    }
}

// ---------------- kernel 5: read partials (direct global, no transpose) ----
__global__ __launch_bounds__(256) void k_read(const float* __restrict__ mem,
                                              const float* __restrict__ wbuf) {
    __shared__ float wsh[8][256];
    __shared__ float red[8][512];
    int b = blockIdx.y, chunk = blockIdx.x;
    int tid = threadIdx.x;
    int w = tid >> 5, lane = tid & 31;
    float2 acc[8];
#pragma unroll
    for (int h = 0; h < 8; h++) acc[h] = make_float2(0.f, 0.f);

    const float2* mrow = (const float2*)(mem + ((size_t)b * N_ + (size_t)chunk * CHUNK_N) * M_);

    for (int st = 0; st < CHUNK_N; st += 256) {
#pragma unroll
        for (int i = 0; i < 8; i++) {
            int idx = tid + i * 256;
            int hh = idx >> 8, nn = idx & 255;
            wsh[hh][nn] = wbuf[((size_t)(b * 8 + hh)) * N_ + chunk * CHUNK_N + st + nn];
        }
        __syncthreads();
#pragma unroll 4
        for (int j = 0; j < 32; j++) {
            int nl = w * 32 + j;
            int n = st + nl;
            float2 mv = mrow[(size_t)n * 32 + lane];
#pragma unroll
            for (int h = 0; h < 8; h++) {
                float wv = wsh[h][nl];
                acc[h].x = fmaf(wv, mv.x, acc[h].x);
                acc[h].y = fmaf(wv, mv.y, acc[h].y);
            }
        }
        __syncthreads();
    }
#pragma unroll
    for (int h = 0; h < 8; h++) {
        red[w][h * 64 + lane * 2]     = acc[h].x;
        red[w][h * 64 + lane * 2 + 1] = acc[h].y;
    }
    __syncthreads();
#pragma unroll
    for (int r = 0; r < 2; r++) {
        int i = tid + r * 256;
        float s = 0.f;
#pragma unroll
        for (int ww = 0; ww < 8; ww++) s += red[ww][i];
        g_partial[((size_t)chunk * B_ + b) * 512 + i] = s;
    }
}

// ---------------- kernel 6: reduce partials -> read_data --------------------
__global__ __launch_bounds__(256) void k_final(float* __restrict__ out) {
    int i = blockIdx.x * 256 + threadIdx.x;  // < 32768
    float s = 0.f;
#pragma unroll
    for (int c = 0; c < NCHUNK; c++)
        s += g_partial[(size_t)c * BH_ * M_ + i];
    out[i] = s;
}

// ---------------- launch -----------------------------------------------------
extern "C" void kernel_launch(void* const* d_in, const int* in_sizes, int n_in,
                              void* d_out, int out_size) {
    const float* x     = (const float*)d_in[0];
    const float* mem   = (const float*)d_in[1];
    const float* wprev = (const float*)d_in[2];
    const float* W     = (const float*)d_in[3];
    const float* bias  = (const float*)d_in[4];
    float* out = (float*)d_out;
    float* out_read = out;                         // 32768
    float* out_w    = out + 32768;                 // 8388608
    float* out_e    = out + 32768 + (size_t)BH_ * N_;
    float* out_a    = out_e + 32768;

    cudaFuncSetAttribute(k_cos,  cudaFuncAttributeMaxDynamicSharedMemorySize, TILE_R * PITCH * 4);
    cudaFuncSetAttribute(k_addr, cudaFuncAttributeMaxDynamicSharedMemorySize, N_ * 4);

    k_gemm<<<dim3(50, KSPLIT), 256>>>(x, W);
    k_act<<<BH_, 64>>>(bias, out_e, out_a);
    k_cos<<<dim3(NCHUNK, B_), 256, TILE_R * PITCH * 4>>>(mem, out_w);
    k_addr<<<BH_, 512, N_ * 4>>>(out_w, wprev);
    k_read<<<dim3(NCHUNK, B_), 256>>>(mem, out_w);
    k_final<<<128, 256>>>(out_read);
}